// round 4
// baseline (speedup 1.0000x reference)
#include <cuda_runtime.h>
#include <cuda_bf16.h>
#include <math.h>

// Problem constants
#define B_   2
#define S_   2048
#define D_   1024
#define H_   16
#define HD_  64
#define BH_  32          // B_*H_
#define M1_  4096        // B_*S_

// ---------------------------------------------------------------------------
// Scratch (static device globals; no runtime allocation allowed)
// ---------------------------------------------------------------------------
__device__ float g_q[M1_ * D_];                       // 16 MB
__device__ float g_k[M1_ * D_];                       // 16 MB
__device__ float g_v[M1_ * D_];                       // 16 MB
__device__ float g_scores[(long)BH_ * S_ * S_];       // 512 MB
__device__ float g_cmax[BH_ * S_];                    // column max
__device__ float g_cden[BH_ * S_];                    // column denom
__device__ float g_attn[M1_ * D_];                    // 16 MB

// ---------------------------------------------------------------------------
// Generic tiled SGEMM:
//   C = epilogue( A[M,K] @ op(B) )   op(B) = B[N,K]^T if TRANSB else B[K,N]
// Batched over blockIdx.z with (batch, head) stride decomposition:
//   z -> b = z/16, h = z%16 ; ptr += b*s?b + h*s?h
// Epilogue options:
//   BIAS:      C += bias[col]
//   MASKSCALE: v = v*scale; if (mask[row*N+col]==0) v = -10000
// Loader option:
//   SOFTA: A element (i, kk) -> exp(a - cmax[z*K + kk]) / cden[z*K + kk]
// ---------------------------------------------------------------------------
template<int BM, int BN, int BK, int TM, int TN,
         bool TRANSB, bool BIAS, bool MASKSCALE, bool SOFTA>
__global__ __launch_bounds__((BM / TM) * (BN / TN))
void gemm_kernel(const float* __restrict__ A, const float* __restrict__ Bm,
                 float* __restrict__ C, const float* __restrict__ bias,
                 const int* __restrict__ mask,
                 const float* __restrict__ cm, const float* __restrict__ cd,
                 int M, int N, int K, int lda, int ldb, int ldc,
                 long sAb, long sAh, long sBb, long sBh, long sCb, long sCh,
                 float scale)
{
    constexpr int NT = (BM / TM) * (BN / TN);

    const int z = blockIdx.z;
    const int bb = z >> 4;
    const int hh = z & 15;
    A  += bb * sAb + hh * sAh;
    Bm += bb * sBb + hh * sBh;
    C  += bb * sCb + hh * sCh;
    if (SOFTA) { cm += (long)z * K; cd += (long)z * K; }

    __shared__ float As[BK][BM];
    __shared__ float Bs[BK][BN];

    const int tid = threadIdx.x;
    const int tx  = tid % (BN / TN);
    const int ty  = tid / (BN / TN);
    const int m0  = blockIdx.y * BM;
    const int n0  = blockIdx.x * BN;

    float acc[TM][TN];
#pragma unroll
    for (int i = 0; i < TM; i++)
#pragma unroll
        for (int j = 0; j < TN; j++) acc[i][j] = 0.f;

    for (int kt = 0; kt < K; kt += BK) {
        // ---- load A tile (BM x BK), stored transposed As[k][m] ----
        constexpr int A4 = BM * BK / 4;
#pragma unroll
        for (int t = tid; t < A4; t += NT) {
            const int r = t / (BK / 4);
            const int c = (t % (BK / 4)) * 4;
            const float4 va = *reinterpret_cast<const float4*>(
                &A[(long)(m0 + r) * lda + kt + c]);
            float x0 = va.x, x1 = va.y, x2 = va.z, x3 = va.w;
            if (SOFTA) {
                x0 = __expf(x0 - cm[kt + c + 0]) / cd[kt + c + 0];
                x1 = __expf(x1 - cm[kt + c + 1]) / cd[kt + c + 1];
                x2 = __expf(x2 - cm[kt + c + 2]) / cd[kt + c + 2];
                x3 = __expf(x3 - cm[kt + c + 3]) / cd[kt + c + 3];
            }
            As[c + 0][r] = x0; As[c + 1][r] = x1;
            As[c + 2][r] = x2; As[c + 3][r] = x3;
        }
        // ---- load B tile ----
        if (TRANSB) {
            constexpr int B4 = BN * BK / 4;
#pragma unroll
            for (int t = tid; t < B4; t += NT) {
                const int r = t / (BK / 4);
                const int c = (t % (BK / 4)) * 4;
                const float4 vb = *reinterpret_cast<const float4*>(
                    &Bm[(long)(n0 + r) * ldb + kt + c]);
                Bs[c + 0][r] = vb.x; Bs[c + 1][r] = vb.y;
                Bs[c + 2][r] = vb.z; Bs[c + 3][r] = vb.w;
            }
        } else {
            constexpr int B4 = BK * BN / 4;
#pragma unroll
            for (int t = tid; t < B4; t += NT) {
                const int r = t / (BN / 4);
                const int c = (t % (BN / 4)) * 4;
                const float4 vb = *reinterpret_cast<const float4*>(
                    &Bm[(long)(kt + r) * ldb + n0 + c]);
                *reinterpret_cast<float4*>(&Bs[r][c]) = vb;
            }
        }
        __syncthreads();

        // ---- compute ----
#pragma unroll
        for (int k = 0; k < BK; k++) {
            float af[TM], bf[TN];
#pragma unroll
            for (int i = 0; i < TM; i++) af[i] = As[k][ty * TM + i];
#pragma unroll
            for (int j = 0; j < TN; j++) bf[j] = Bs[k][tx * TN + j];
#pragma unroll
            for (int i = 0; i < TM; i++)
#pragma unroll
                for (int j = 0; j < TN; j++)
                    acc[i][j] = fmaf(af[i], bf[j], acc[i][j]);
        }
        __syncthreads();
    }

    // ---- epilogue (float4 stores) ----
#pragma unroll
    for (int i = 0; i < TM; i++) {
        const int row = m0 + ty * TM + i;
#pragma unroll
        for (int j0 = 0; j0 < TN; j0 += 4) {
            float tmp[4];
#pragma unroll
            for (int j = 0; j < 4; j++) {
                const int col = n0 + tx * TN + j0 + j;
                float v = acc[i][j0 + j];
                if (MASKSCALE) {
                    v *= scale;
                    if (mask[(long)row * N + col] == 0) v = -10000.0f;
                }
                if (BIAS) v += bias[col];
                tmp[j] = v;
            }
            *reinterpret_cast<float4*>(
                &C[(long)row * ldc + n0 + tx * TN + j0]) =
                make_float4(tmp[0], tmp[1], tmp[2], tmp[3]);
        }
    }
}

// ---------------------------------------------------------------------------
// Column-wise online softmax stats over the query axis i:
//   m[z,j] = max_i s[z,i,j],  d[z,j] = sum_i exp(s[z,i,j] - m[z,j])
// Block of 256 threads handles 256 consecutive columns -> coalesced row reads.
// ---------------------------------------------------------------------------
__global__ __launch_bounds__(256)
void colstats_kernel(const float* __restrict__ Smat,
                     float* __restrict__ m, float* __restrict__ d)
{
    const int z = blockIdx.y;
    const int j = blockIdx.x * blockDim.x + threadIdx.x;
    const float* p = Smat + (long)z * S_ * S_ + j;

    float mx  = -3.0e38f;
    float sum = 0.0f;
#pragma unroll 4
    for (int i = 0; i < S_; i++) {
        const float v = p[(long)i * S_];
        if (v > mx) {
            sum = sum * __expf(mx - v) + 1.0f;
            mx  = v;
        } else {
            sum += __expf(v - mx);
        }
    }
    m[z * S_ + j] = mx;
    d[z * S_ + j] = sum;
}

// ---------------------------------------------------------------------------
// Host launcher
// ---------------------------------------------------------------------------
extern "C" void kernel_launch(void* const* d_in, const int* in_sizes, int n_in,
                              void* d_out, int out_size)
{
    const float* query = (const float*)d_in[0];
    const float* key_  = (const float*)d_in[1];
    const float* value = (const float*)d_in[2];
    const int*   mask  = (const int*)d_in[3];
    const float* Wq = (const float*)d_in[4];
    const float* bq = (const float*)d_in[5];
    const float* Wk = (const float*)d_in[6];
    const float* bk = (const float*)d_in[7];
    const float* Wv = (const float*)d_in[8];
    const float* bv = (const float*)d_in[9];
    const float* Wp = (const float*)d_in[10];
    const float* bp = (const float*)d_in[11];
    float* out = (float*)d_out;

    float *q, *k, *v, *sc, *cm, *cd, *at;
    cudaGetSymbolAddress((void**)&q,  g_q);
    cudaGetSymbolAddress((void**)&k,  g_k);
    cudaGetSymbolAddress((void**)&v,  g_v);
    cudaGetSymbolAddress((void**)&sc, g_scores);
    cudaGetSymbolAddress((void**)&cm, g_cmax);
    cudaGetSymbolAddress((void**)&cd, g_cden);
    cudaGetSymbolAddress((void**)&at, g_attn);

    const long SD  = (long)S_ * D_;          // 2 097 152
    const long SS  = (long)S_ * S_;          // 4 194 304
    const long HSS = (long)H_ * SS;          // 67 108 864

    // ---- 1..3: Q/K/V projections: [4096,1024] = X @ W^T + b ----
    {
        dim3 grid(D_ / 128, M1_ / 128, 1);
        gemm_kernel<128, 128, 16, 8, 8, true, true, false, false>
            <<<grid, 256>>>(query, Wq, q, bq, nullptr, nullptr, nullptr,
                            M1_, D_, D_, D_, D_, D_,
                            0, 0, 0, 0, 0, 0, 1.0f);
        gemm_kernel<128, 128, 16, 8, 8, true, true, false, false>
            <<<grid, 256>>>(key_, Wk, k, bk, nullptr, nullptr, nullptr,
                            M1_, D_, D_, D_, D_, D_,
                            0, 0, 0, 0, 0, 0, 1.0f);
        gemm_kernel<128, 128, 16, 8, 8, true, true, false, false>
            <<<grid, 256>>>(value, Wv, v, bv, nullptr, nullptr, nullptr,
                            M1_, D_, D_, D_, D_, D_,
                            0, 0, 0, 0, 0, 0, 1.0f);
    }

    // ---- 4: scores[z,i,j] = 0.25 * q_h[i,:] . k_h[j,:], masked ----
    {
        dim3 grid(S_ / 128, S_ / 128, BH_);
        gemm_kernel<128, 128, 16, 8, 8, true, false, true, false>
            <<<grid, 256>>>(q, k, sc, nullptr, mask, nullptr, nullptr,
                            S_, S_, HD_, D_, D_, S_,
                            SD, HD_, SD, HD_, HSS, SS, 0.25f);
    }

    // ---- 5: per-column (axis=i) softmax stats ----
    {
        dim3 grid(S_ / 256, BH_);
        colstats_kernel<<<grid, 256>>>(sc, cm, cd);
    }

    // ---- 6: attn @ V with softmax fused into A loader ----
    {
        dim3 grid(HD_ / 64, S_ / 128, BH_);
        gemm_kernel<128, 64, 16, 8, 4, false, false, false, true>
            <<<grid, 256>>>(sc, v, at, nullptr, nullptr, cm, cd,
                            S_, HD_, S_, S_, D_, D_,
                            HSS, SS, SD, HD_, SD, HD_, 1.0f);
    }

    // ---- 7: output projection -> d_out ----
    {
        dim3 grid(D_ / 128, M1_ / 128, 1);
        gemm_kernel<128, 128, 16, 8, 8, true, true, false, false>
            <<<grid, 256>>>(at, Wp, out, bp, nullptr, nullptr, nullptr,
                            M1_, D_, D_, D_, D_, D_,
                            0, 0, 0, 0, 0, 0, 1.0f);
    }
}

// round 6
// speedup vs baseline: 2.1085x; 2.1085x over previous
#include <cuda_runtime.h>
#include <cuda_bf16.h>
#include <stdint.h>

#define S_  2048
#define D_  1024
#define HD_ 64
#define M1_ 4096
#define BHN 32
#define SSl ((long)S_ * S_)

__device__ float g_q[M1_ * D_], g_k[M1_ * D_], g_v[M1_ * D_], g_at[M1_ * D_];
__device__ float g_vt[BHN * HD_ * S_];
__device__ float g_sc[(long)BHN * SSl];
__device__ float g_cm[BHN * S_], g_cd[BHN * S_];

// ---------------- helpers ----------------
__device__ __forceinline__ uint32_t smem_u32(const void* p) {
    uint32_t a;
    asm("{ .reg .u64 t; cvta.to.shared.u64 t, %1; cvt.u32.u64 %0, t; }" : "=r"(a) : "l"(p));
    return a;
}
__device__ __forceinline__ void ldm_x4(uint32_t* r, uint32_t addr) {
    asm volatile("ldmatrix.sync.aligned.m8n8.x4.shared.b16 {%0,%1,%2,%3}, [%4];"
                 : "=r"(r[0]), "=r"(r[1]), "=r"(r[2]), "=r"(r[3]) : "r"(addr));
}
__device__ __forceinline__ void ldm_x2(uint32_t* r, uint32_t addr) {
    asm volatile("ldmatrix.sync.aligned.m8n8.x2.shared.b16 {%0,%1}, [%2];"
                 : "=r"(r[0]), "=r"(r[1]) : "r"(addr));
}
__device__ __forceinline__ void mma16816(float* c, const uint32_t* a, const uint32_t* b) {
    asm volatile(
        "mma.sync.aligned.m16n8k16.row.col.f32.bf16.bf16.f32 "
        "{%0,%1,%2,%3}, {%4,%5,%6,%7}, {%8,%9}, {%0,%1,%2,%3};"
        : "+f"(c[0]), "+f"(c[1]), "+f"(c[2]), "+f"(c[3])
        : "r"(a[0]), "r"(a[1]), "r"(a[2]), "r"(a[3]), "r"(b[0]), "r"(b[1]));
}
__device__ __forceinline__ uint32_t pk2(float a, float b) {
    __nv_bfloat162 t = __floats2bfloat162_rn(a, b);
    return *(uint32_t*)&t;
}
// split one float4 into hi/lo bf16 pairs (packed)
__device__ __forceinline__ void split4(float4 v, uint2& h, uint2& l) {
    __nv_bfloat16 h0 = __float2bfloat16(v.x), h1 = __float2bfloat16(v.y);
    __nv_bfloat16 h2 = __float2bfloat16(v.z), h3 = __float2bfloat16(v.w);
    h.x = ((uint32_t)__bfloat16_as_ushort(h1) << 16) | __bfloat16_as_ushort(h0);
    h.y = ((uint32_t)__bfloat16_as_ushort(h3) << 16) | __bfloat16_as_ushort(h2);
    l.x = pk2(v.x - __bfloat162float(h0), v.y - __bfloat162float(h1));
    l.y = pk2(v.z - __bfloat162float(h2), v.w - __bfloat162float(h3));
}

// ---------------------------------------------------------------------------
// Split-bf16 mma.sync GEMM: C[128, NT] = A[128,K] . B[NT,K]^T  (A,B K-major fp32)
//   C ~= AhBh + AhBl + AlBh  (fp32 accum)
// EPI: 0 = fp32 out (+bias if non-null); 1 = v*scale then mask==0 -> -10000
// SOFTA: A element (i,k) -> exp(a - cm[k]) / cd[k]     (column softmax fusion)
// 256 threads = 8 warps in 4(M) x 2(N); warp tile 32 x (NT/2); BK=32.
// Smem tile rows = 64B (32 bf16), chunk-swizzled: chunk' = chunk ^ ((row>>1)&3)
// ---------------------------------------------------------------------------
template<int NT, int EPI, bool SOFTA>
__global__ __launch_bounds__(256, 2)
void mma_gemm(const float* __restrict__ A, const float* __restrict__ B,
              float* __restrict__ C, const float* __restrict__ bias,
              const int* __restrict__ mask, const float* __restrict__ cm,
              const float* __restrict__ cd,
              int lda, int ldb, int ldc, int K,
              long sAb, long sAh, long sBb, long sBh, long sCb, long sCh,
              float scale)
{
    constexpr int WN = NT / 2;    // warp n-extent
    constexpr int NB = WN / 8;    // B frags per warp
    __shared__ __align__(128) uint8_t smAh[128 * 64], smAl[128 * 64];
    __shared__ __align__(128) uint8_t smBh[NT * 64],  smBl[NT * 64];

    const int tid = threadIdx.x, wid = tid >> 5, lane = tid & 31;
    const int wm = wid >> 1, wn = wid & 1;
    const int z = blockIdx.z, bb = z >> 4, hh = z & 15;
    const int m0 = blockIdx.y * 128, n0 = blockIdx.x * NT;

    A += bb * sAb + hh * sAh;
    B += bb * sBb + hh * sBh;
    C += bb * sCb + hh * sCh;
    if (SOFTA) { cm += (long)z * S_; cd += (long)z * S_; }

    const uint32_t bAh = smem_u32(smAh), bAl = smem_u32(smAl);
    const uint32_t bBh = smem_u32(smBh), bBl = smem_u32(smBl);

    // ldmatrix lane address components
    const int rA = wm * 32 + (lane & 15);       // A row (mt adds 16; swz invariant)
    const int cpA = (lane >> 4) & 1;            // A chunk parity
    const int swA = (rA >> 1) & 3;
    const int rB = wn * WN + (lane & 7);        // B row (nt adds 8; swz invariant)
    const int cpB = (lane >> 3) & 1;
    const int swB = (rB >> 1) & 3;

    float acc[2][NB][4];
#pragma unroll
    for (int i = 0; i < 2; i++)
#pragma unroll
        for (int j = 0; j < NB; j++)
#pragma unroll
            for (int e = 0; e < 4; e++) acc[i][j][e] = 0.f;

    const int nch = K / 32;
    for (int c = 0; c < nch; c++) {
        const int kt = c * 32;
        __syncthreads();
        // ---- A tile: 128 x 32 fp32 -> split bf16 ----
#pragma unroll
        for (int p = 0; p < 4; p++) {
            const int e = p * 256 + tid;
            const int r = e >> 3, j4 = (e & 7) * 4;
            float4 v = *(const float4*)(A + (long)(m0 + r) * lda + kt + j4);
            if (SOFTA) {
                const int g = kt + j4;
                v.x = __fdividef(__expf(v.x - cm[g + 0]), cd[g + 0]);
                v.y = __fdividef(__expf(v.y - cm[g + 1]), cd[g + 1]);
                v.z = __fdividef(__expf(v.z - cm[g + 2]), cd[g + 2]);
                v.w = __fdividef(__expf(v.w - cm[g + 3]), cd[g + 3]);
            }
            uint2 h, l; split4(v, h, l);
            const int ch = j4 >> 3;
            const int off = (r * 4 + (ch ^ ((r >> 1) & 3))) * 16 + (j4 & 4) * 2;
            *(uint2*)(smAh + off) = h;
            *(uint2*)(smAl + off) = l;
        }
        // ---- B tile: NT x 32 fp32 -> split bf16 ----
#pragma unroll
        for (int p = 0; p < NT / 32; p++) {
            const int e = p * 256 + tid;
            const int r = e >> 3, j4 = (e & 7) * 4;
            const float4 v = *(const float4*)(B + (long)(n0 + r) * ldb + kt + j4);
            uint2 h, l; split4(v, h, l);
            const int ch = j4 >> 3;
            const int off = (r * 4 + (ch ^ ((r >> 1) & 3))) * 16 + (j4 & 4) * 2;
            *(uint2*)(smBh + off) = h;
            *(uint2*)(smBl + off) = l;
        }
        __syncthreads();

        // ---- compute: 2 k16 steps ----
#pragma unroll
        for (int ks = 0; ks < 2; ks++) {
            const int cA = (2 * ks + cpA) ^ swA;
            uint32_t ah0[4], ah1[4], al0[4], al1[4];
            ldm_x4(ah0, bAh + (rA * 4 + cA) * 16);
            ldm_x4(ah1, bAh + ((rA + 16) * 4 + cA) * 16);
            ldm_x4(al0, bAl + (rA * 4 + cA) * 16);
            ldm_x4(al1, bAl + ((rA + 16) * 4 + cA) * 16);
            const int cB = (2 * ks + cpB) ^ swB;
#pragma unroll
            for (int nt = 0; nt < NB; nt++) {
                uint32_t bh[2], bl[2];
                const uint32_t ob = ((rB + nt * 8) * 4 + cB) * 16;
                ldm_x2(bh, bBh + ob);
                ldm_x2(bl, bBl + ob);
                mma16816(acc[0][nt], ah0, bh);
                mma16816(acc[0][nt], ah0, bl);
                mma16816(acc[0][nt], al0, bh);
                mma16816(acc[1][nt], ah1, bh);
                mma16816(acc[1][nt], ah1, bl);
                mma16816(acc[1][nt], al1, bh);
            }
        }
    }

    // ---- epilogue ----
    const int gid = lane >> 2, qid = lane & 3;
#pragma unroll
    for (int mt = 0; mt < 2; mt++) {
        const int r0 = m0 + wm * 32 + mt * 16 + gid;
#pragma unroll
        for (int nt = 0; nt < NB; nt++) {
            const int col = n0 + wn * WN + nt * 8 + qid * 2;
            float2 v0 = make_float2(acc[mt][nt][0], acc[mt][nt][1]);
            float2 v1 = make_float2(acc[mt][nt][2], acc[mt][nt][3]);
            if (EPI == 1) {
                v0.x *= scale; v0.y *= scale; v1.x *= scale; v1.y *= scale;
                const int2 m0v = *(const int2*)(mask + (long)r0 * S_ + col);
                const int2 m1v = *(const int2*)(mask + (long)(r0 + 8) * S_ + col);
                if (m0v.x == 0) v0.x = -10000.0f;
                if (m0v.y == 0) v0.y = -10000.0f;
                if (m1v.x == 0) v1.x = -10000.0f;
                if (m1v.y == 0) v1.y = -10000.0f;
            } else if (bias) {
                const float b0 = bias[col], b1 = bias[col + 1];
                v0.x += b0; v0.y += b1; v1.x += b0; v1.y += b1;
            }
            *(float2*)(C + (long)r0 * ldc + col) = v0;
            *(float2*)(C + (long)(r0 + 8) * ldc + col) = v1;
        }
    }
}

// ---- V transpose per head: v[4096,1024] -> vt[z][n=64][j=2048] ----
__global__ __launch_bounds__(256)
void vtrans_kernel(const float* __restrict__ v, float* __restrict__ vt) {
    __shared__ float t[64][65];
    const int z = blockIdx.y, jt = blockIdx.x * 64;
    const int b = z >> 4, h = z & 15;
    const float* src = v + ((long)b * S_ + jt) * D_ + h * HD_;
    for (int i = threadIdx.x; i < 64 * 64; i += 256)
        t[i >> 6][i & 63] = src[(long)(i >> 6) * D_ + (i & 63)];
    __syncthreads();
    float* dst = vt + (long)z * HD_ * S_ + jt;
    for (int i = threadIdx.x; i < 64 * 64; i += 256)
        dst[(long)(i >> 6) * S_ + (i & 63)] = t[i & 63][i >> 6];
}

// ---- column (axis = query i) softmax stats ----
__global__ __launch_bounds__(256)
void colstats_kernel(const float* __restrict__ Smat, float* __restrict__ m,
                     float* __restrict__ d) {
    const int z = blockIdx.y;
    const int j = blockIdx.x * 256 + threadIdx.x;
    const float* p = Smat + (long)z * SSl + j;
    float mx = -3.0e38f, sum = 0.0f;
#pragma unroll 4
    for (int i = 0; i < S_; i++) {
        const float v = p[(long)i * S_];
        if (v > mx) { sum = sum * __expf(mx - v) + 1.0f; mx = v; }
        else        { sum += __expf(v - mx); }
    }
    m[z * S_ + j] = mx;
    d[z * S_ + j] = sum;
}

// ---------------------------------------------------------------------------
extern "C" void kernel_launch(void* const* d_in, const int* in_sizes, int n_in,
                              void* d_out, int out_size)
{
    const float* query = (const float*)d_in[0];
    const float* key_  = (const float*)d_in[1];
    const float* value = (const float*)d_in[2];
    const int*   mask  = (const int*)d_in[3];
    const float* Wq = (const float*)d_in[4];
    const float* bq = (const float*)d_in[5];
    const float* Wk = (const float*)d_in[6];
    const float* bk = (const float*)d_in[7];
    const float* Wv = (const float*)d_in[8];
    const float* bv = (const float*)d_in[9];
    const float* Wp = (const float*)d_in[10];
    const float* bp = (const float*)d_in[11];
    float* out = (float*)d_out;

    float *q, *k, *v, *at, *vt, *sc, *cm, *cd;
    cudaGetSymbolAddress((void**)&q,  g_q);
    cudaGetSymbolAddress((void**)&k,  g_k);
    cudaGetSymbolAddress((void**)&v,  g_v);
    cudaGetSymbolAddress((void**)&at, g_at);
    cudaGetSymbolAddress((void**)&vt, g_vt);
    cudaGetSymbolAddress((void**)&sc, g_sc);
    cudaGetSymbolAddress((void**)&cm, g_cm);
    cudaGetSymbolAddress((void**)&cd, g_cd);

    const long SD  = (long)S_ * D_;
    const long HSS = 16 * SSl;

    // Q/K/V projections: [4096,1024] = X @ W^T + b
    dim3 gp(D_ / 128, M1_ / 128, 1);
    mma_gemm<128, 0, false><<<gp, 256>>>(query, Wq, q, bq, nullptr, nullptr, nullptr,
        D_, D_, D_, D_, 0, 0, 0, 0, 0, 0, 0.f);
    mma_gemm<128, 0, false><<<gp, 256>>>(key_, Wk, k, bk, nullptr, nullptr, nullptr,
        D_, D_, D_, D_, 0, 0, 0, 0, 0, 0, 0.f);
    mma_gemm<128, 0, false><<<gp, 256>>>(value, Wv, v, bv, nullptr, nullptr, nullptr,
        D_, D_, D_, D_, 0, 0, 0, 0, 0, 0, 0.f);

    // V transpose per head
    vtrans_kernel<<<dim3(S_ / 64, BHN), 256>>>(v, vt);

    // scores = 0.25 * q_h @ k_h^T, masked
    mma_gemm<128, 1, false><<<dim3(S_ / 128, S_ / 128, BHN), 256>>>(
        q, k, sc, nullptr, mask, nullptr, nullptr,
        D_, D_, S_, HD_, SD, HD_, SD, HD_, HSS, SSl, 0.25f);

    // column softmax stats
    colstats_kernel<<<dim3(S_ / 256, BHN), 256>>>(sc, cm, cd);

    // attn @ V (softmax fused into A loader)
    mma_gemm<64, 0, true><<<dim3(1, S_ / 128, BHN), 256>>>(
        sc, vt, at, nullptr, nullptr, cm, cd,
        S_, S_, D_, S_, HSS, SSl, (long)16 * HD_ * S_, (long)HD_ * S_, SD, HD_, 0.f);

    // output projection -> d_out
    mma_gemm<128, 0, false><<<gp, 256>>>(at, Wp, out, bp, nullptr, nullptr, nullptr,
        D_, D_, D_, D_, 0, 0, 0, 0, 0, 0, 0.f);
}

// round 7
// speedup vs baseline: 3.5998x; 1.7073x over previous
#include <cuda_runtime.h>
#include <cuda_bf16.h>
#include <stdint.h>

#define S_  2048
#define D_  1024
#define HD_ 64
#define M1_ 4096
#define BHN 32
#define SSl ((long)S_ * S_)

typedef unsigned short u16;

// ---------------- static scratch ----------------
__device__ u16 cqh[M1_ * D_], cql[M1_ * D_];   // converted query
__device__ u16 ckh[M1_ * D_], ckl[M1_ * D_];   // converted key
__device__ u16 cvh[M1_ * D_], cvl[M1_ * D_];   // converted value
__device__ u16 wqh[D_ * D_], wql[D_ * D_];
__device__ u16 wkh[D_ * D_], wkl[D_ * D_];
__device__ u16 wvh[D_ * D_], wvl[D_ * D_];
__device__ u16 wph[D_ * D_], wpl[D_ * D_];
__device__ u16 qhA[M1_ * D_], qlA[M1_ * D_];   // projected Q (split)
__device__ u16 khA[M1_ * D_], klA[M1_ * D_];   // projected K
__device__ u16 vhA[M1_ * D_], vlA[M1_ * D_];   // projected V
__device__ u16 vth[BHN * HD_ * S_], vtl[BHN * HD_ * S_];  // V^T per head
__device__ u16 athA[M1_ * D_], atlA[M1_ * D_]; // attn output (split)
__device__ float g_sc[(long)BHN * SSl];        // scores fp32 (512 MB)
__device__ float g_pm[BHN * 16 * S_], g_pd[BHN * 16 * S_];
__device__ float g_cm[BHN * S_], g_cd[BHN * S_];

// ---------------- helpers ----------------
__device__ __forceinline__ uint32_t smem_u32(const void* p) {
    uint32_t a;
    asm("{ .reg .u64 t; cvta.to.shared.u64 t, %1; cvt.u32.u64 %0, t; }" : "=r"(a) : "l"(p));
    return a;
}
__device__ __forceinline__ void cpa16(uint32_t d, const void* s) {
    asm volatile("cp.async.cg.shared.global [%0], [%1], 16;" :: "r"(d), "l"(s));
}
#define CPC()  asm volatile("cp.async.commit_group;" ::: "memory")
#define CPW1() asm volatile("cp.async.wait_group 1;" ::: "memory")
#define CPW0() asm volatile("cp.async.wait_group 0;" ::: "memory")

__device__ __forceinline__ void ldm_x4(uint32_t* r, uint32_t addr) {
    asm volatile("ldmatrix.sync.aligned.m8n8.x4.shared.b16 {%0,%1,%2,%3}, [%4];"
                 : "=r"(r[0]), "=r"(r[1]), "=r"(r[2]), "=r"(r[3]) : "r"(addr));
}
__device__ __forceinline__ void ldm_x2(uint32_t* r, uint32_t addr) {
    asm volatile("ldmatrix.sync.aligned.m8n8.x2.shared.b16 {%0,%1}, [%2];"
                 : "=r"(r[0]), "=r"(r[1]) : "r"(addr));
}
__device__ __forceinline__ void mma16816(float* c, const uint32_t* a, const uint32_t* b) {
    asm volatile(
        "mma.sync.aligned.m16n8k16.row.col.f32.bf16.bf16.f32 "
        "{%0,%1,%2,%3}, {%4,%5,%6,%7}, {%8,%9}, {%0,%1,%2,%3};"
        : "+f"(c[0]), "+f"(c[1]), "+f"(c[2]), "+f"(c[3])
        : "r"(a[0]), "r"(a[1]), "r"(a[2]), "r"(a[3]), "r"(b[0]), "r"(b[1]));
}
__device__ __forceinline__ uint32_t pk2(float a, float b) {
    __nv_bfloat162 t = __floats2bfloat162_rn(a, b);
    return *(uint32_t*)&t;
}
__device__ __forceinline__ void split2(float a, float b, uint32_t& h, uint32_t& l) {
    __nv_bfloat16 h0 = __float2bfloat16(a), h1 = __float2bfloat16(b);
    h = ((uint32_t)__bfloat16_as_ushort(h1) << 16) | __bfloat16_as_ushort(h0);
    l = pk2(a - __bfloat162float(h0), b - __bfloat162float(h1));
}
__device__ __forceinline__ void split4(float4 v, uint2& h, uint2& l) {
    split2(v.x, v.y, h.x, l.x);
    split2(v.z, v.w, h.y, l.y);
}

// ---------------------------------------------------------------------------
// Pipelined split-bf16 mma.sync GEMM: C[128, NT] = A[128,K] . B[NT,K]^T
//   C ~= AhBh + AhBl + AlBh (fp32 accum)
// !SOFTA: A preconverted (Ah,Al) bf16, cp.async. SOFTA: A = softmax of fp32 Af.
// B always preconverted (Bh,Bl) bf16, cp.async double-buffered.
// EPI 0: fp32 + bias; 1: scores (scale, mask, fp32 out, column stats partials);
//     2: split-bf16 out (+bias if non-null)
// ---------------------------------------------------------------------------
template<int NT, int EPI, bool SOFTA>
__global__ __launch_bounds__(256, 2)
void mma_gemm(const u16* __restrict__ Ah, const u16* __restrict__ Al,
              const float* __restrict__ Af,
              const u16* __restrict__ Bh, const u16* __restrict__ Bl,
              float* __restrict__ Cf, u16* __restrict__ Ch, u16* __restrict__ Cl,
              const float* __restrict__ bias, const int* __restrict__ mask,
              const float* __restrict__ cm, const float* __restrict__ cd,
              float* __restrict__ pm, float* __restrict__ pd,
              int lda, int ldb, int ldc, int K,
              long sAb, long sAh_, long sBb, long sBh_, long sCb, long sCh_,
              float scale)
{
    constexpr int WN  = NT / 2;
    constexpr int NB  = WN / 8;
    constexpr int BSZ = NT * 64;      // bytes per B array per stage
    constexpr int BOFF = 32768;       // A stages: 2 x (8K hi + 8K lo)
    extern __shared__ __align__(128) uint8_t sm[];
    const uint32_t smb = smem_u32(sm);

    const int tid = threadIdx.x, wid = tid >> 5, lane = tid & 31;
    const int wm = wid >> 1, wn = wid & 1;
    const int z = blockIdx.z, bb = z >> 4, hh = z & 15;
    const int m0 = blockIdx.y * 128, n0 = blockIdx.x * NT;

    if (SOFTA) { Af += bb * sAb + hh * sAh_; cm += (long)z * S_; cd += (long)z * S_; }
    else       { Ah += bb * sAb + hh * sAh_; Al += bb * sAb + hh * sAh_; }
    Bh += bb * sBb + hh * sBh_;  Bl += bb * sBb + hh * sBh_;
    if (EPI == 2) { Ch += bb * sCb + hh * sCh_; Cl += bb * sCb + hh * sCh_; }
    else          { Cf += bb * sCb + hh * sCh_; }

    float4 areg[4];
    auto issueA = [&](int c, int s) {
#pragma unroll
        for (int p = 0; p < 2; p++) {
            const int e = p * 256 + tid, r = e >> 2, ch = e & 3;
            const uint32_t off = (uint32_t)(r * 4 + (ch ^ ((r >> 1) & 3))) * 16;
            const long src = (long)(m0 + r) * lda + c * 32 + ch * 8;
            cpa16(smb + s * 16384 + off, Ah + src);
            cpa16(smb + s * 16384 + 8192 + off, Al + src);
        }
    };
    auto issueB = [&](int c, int s) {
#pragma unroll
        for (int p = 0; p < NT * 4 / 256; p++) {
            const int e = p * 256 + tid, r = e >> 2, ch = e & 3;
            const uint32_t off = (uint32_t)(r * 4 + (ch ^ ((r >> 1) & 3))) * 16;
            const long src = (long)(n0 + r) * ldb + c * 32 + ch * 8;
            cpa16(smb + BOFF + s * 2 * BSZ + off, Bh + src);
            cpa16(smb + BOFF + s * 2 * BSZ + BSZ + off, Bl + src);
        }
    };
    auto prefA = [&](int c) {
#pragma unroll
        for (int p = 0; p < 4; p++) {
            const int e = p * 256 + tid, r = e >> 3, j4 = (e & 7) * 4;
            areg[p] = *(const float4*)(Af + (long)(m0 + r) * lda + c * 32 + j4);
        }
    };
    auto stsA = [&](int c, int s) {
#pragma unroll
        for (int p = 0; p < 4; p++) {
            const int e = p * 256 + tid, r = e >> 3, j4 = (e & 7) * 4;
            float4 v = areg[p];
            const int g = c * 32 + j4;
            v.x = __fdividef(__expf(v.x - cm[g + 0]), cd[g + 0]);
            v.y = __fdividef(__expf(v.y - cm[g + 1]), cd[g + 1]);
            v.z = __fdividef(__expf(v.z - cm[g + 2]), cd[g + 2]);
            v.w = __fdividef(__expf(v.w - cm[g + 3]), cd[g + 3]);
            uint2 h, l; split4(v, h, l);
            const uint32_t off = (uint32_t)(r * 4 + ((j4 >> 3) ^ ((r >> 1) & 3))) * 16
                                 + (j4 & 4) * 2;
            *(uint2*)(sm + s * 16384 + off) = h;
            *(uint2*)(sm + s * 16384 + 8192 + off) = l;
        }
    };

    // ldmatrix lane addressing (same layout as proven R6 kernel)
    const int rA = wm * 32 + (lane & 15);
    const int cpA = (lane >> 4) & 1;
    const int swA = (rA >> 1) & 3;
    const int rB = wn * WN + (lane & 7);
    const int cpB = (lane >> 3) & 1;
    const int swB = (rB >> 1) & 3;

    float acc[2][NB][4];
#pragma unroll
    for (int i = 0; i < 2; i++)
#pragma unroll
        for (int j = 0; j < NB; j++)
#pragma unroll
            for (int e = 0; e < 4; e++) acc[i][j][e] = 0.f;

    const int nch = K / 32;
    if (SOFTA) prefA(0); else issueA(0, 0);
    issueB(0, 0);
    CPC();

    for (int c = 0; c < nch; c++) {
        const int s = c & 1;
        if (SOFTA) stsA(c, s);
        const bool more = (c + 1 < nch);
        if (more) {
            if (!SOFTA) issueA(c + 1, s ^ 1);
            issueB(c + 1, s ^ 1);
            CPC();
            if (SOFTA) prefA(c + 1);
            CPW1();
        } else {
            CPW0();
        }
        __syncthreads();

        const uint32_t aBase = smb + s * 16384;
        const uint32_t bBase = smb + BOFF + s * 2 * BSZ;
#pragma unroll
        for (int ks = 0; ks < 2; ks++) {
            const int cA = (2 * ks + cpA) ^ swA;
            uint32_t ah0[4], ah1[4], al0[4], al1[4];
            ldm_x4(ah0, aBase + (rA * 4 + cA) * 16);
            ldm_x4(ah1, aBase + ((rA + 16) * 4 + cA) * 16);
            ldm_x4(al0, aBase + 8192 + (rA * 4 + cA) * 16);
            ldm_x4(al1, aBase + 8192 + ((rA + 16) * 4 + cA) * 16);
            const int cB = (2 * ks + cpB) ^ swB;
#pragma unroll
            for (int nt = 0; nt < NB; nt++) {
                uint32_t bh[2], bl[2];
                const uint32_t ob = ((rB + nt * 8) * 4 + cB) * 16;
                ldm_x2(bh, bBase + ob);
                ldm_x2(bl, bBase + BSZ + ob);
                mma16816(acc[0][nt], ah0, bh);
                mma16816(acc[0][nt], ah0, bl);
                mma16816(acc[0][nt], al0, bh);
                mma16816(acc[1][nt], ah1, bh);
                mma16816(acc[1][nt], ah1, bl);
                mma16816(acc[1][nt], al1, bh);
            }
        }
        __syncthreads();
    }

    // ---- epilogue ----
    const int gid = lane >> 2, qid = lane & 3;
#pragma unroll
    for (int mt = 0; mt < 2; mt++) {
        const int r0 = m0 + wm * 32 + mt * 16 + gid;
#pragma unroll
        for (int nt = 0; nt < NB; nt++) {
            const int col = n0 + wn * WN + nt * 8 + qid * 2;
            float2 v0 = make_float2(acc[mt][nt][0], acc[mt][nt][1]);
            float2 v1 = make_float2(acc[mt][nt][2], acc[mt][nt][3]);
            if (EPI == 1) {
                v0.x *= scale; v0.y *= scale; v1.x *= scale; v1.y *= scale;
                const int2 ma = *(const int2*)(mask + (long)r0 * S_ + col);
                const int2 mb = *(const int2*)(mask + (long)(r0 + 8) * S_ + col);
                if (ma.x == 0) v0.x = -10000.0f;
                if (ma.y == 0) v0.y = -10000.0f;
                if (mb.x == 0) v1.x = -10000.0f;
                if (mb.y == 0) v1.y = -10000.0f;
                *(float2*)(Cf + (long)r0 * ldc + col) = v0;
                *(float2*)(Cf + (long)(r0 + 8) * ldc + col) = v1;
                acc[mt][nt][0] = v0.x; acc[mt][nt][1] = v0.y;
                acc[mt][nt][2] = v1.x; acc[mt][nt][3] = v1.y;
            } else if (EPI == 0) {
                if (bias) {
                    const float b0 = bias[col], b1 = bias[col + 1];
                    v0.x += b0; v0.y += b1; v1.x += b0; v1.y += b1;
                }
                *(float2*)(Cf + (long)r0 * ldc + col) = v0;
                *(float2*)(Cf + (long)(r0 + 8) * ldc + col) = v1;
            } else {
                if (bias) {
                    const float b0 = bias[col], b1 = bias[col + 1];
                    v0.x += b0; v0.y += b1; v1.x += b0; v1.y += b1;
                }
                uint32_t h0, l0, h1, l1;
                split2(v0.x, v0.y, h0, l0);
                split2(v1.x, v1.y, h1, l1);
                *(uint32_t*)(Ch + (long)r0 * ldc + col) = h0;
                *(uint32_t*)(Cl + (long)r0 * ldc + col) = l0;
                *(uint32_t*)(Ch + (long)(r0 + 8) * ldc + col) = h1;
                *(uint32_t*)(Cl + (long)(r0 + 8) * ldc + col) = l1;
            }
        }
    }

    // ---- EPI 1: per-CTA column (query-axis) softmax partial stats ----
    if (EPI == 1) {
        float* smM  = (float*)(sm + BOFF + 4 * BSZ);  // [4][128]
        float* smMF = smM + 512;                      // [128]
        float* smD  = smMF + 128;                     // [4][128]
#pragma unroll
        for (int nt = 0; nt < NB; nt++) {
            float mA = fmaxf(fmaxf(acc[0][nt][0], acc[0][nt][2]),
                             fmaxf(acc[1][nt][0], acc[1][nt][2]));
            float mB = fmaxf(fmaxf(acc[0][nt][1], acc[0][nt][3]),
                             fmaxf(acc[1][nt][1], acc[1][nt][3]));
#pragma unroll
            for (int d = 4; d <= 16; d <<= 1) {
                mA = fmaxf(mA, __shfl_xor_sync(0xffffffffu, mA, d));
                mB = fmaxf(mB, __shfl_xor_sync(0xffffffffu, mB, d));
            }
            if (gid == 0) {
                const int colL = wn * WN + nt * 8 + qid * 2;
                smM[wm * 128 + colL] = mA;
                smM[wm * 128 + colL + 1] = mB;
            }
        }
        __syncthreads();
        if (tid < 128) {
            const float M = fmaxf(fmaxf(smM[tid], smM[128 + tid]),
                                  fmaxf(smM[256 + tid], smM[384 + tid]));
            smMF[tid] = M;
        }
        __syncthreads();
#pragma unroll
        for (int nt = 0; nt < NB; nt++) {
            const int colL = wn * WN + nt * 8 + qid * 2;
            const float MA = smMF[colL], MB = smMF[colL + 1];
            float sA = __expf(acc[0][nt][0] - MA) + __expf(acc[0][nt][2] - MA)
                     + __expf(acc[1][nt][0] - MA) + __expf(acc[1][nt][2] - MA);
            float sB = __expf(acc[0][nt][1] - MB) + __expf(acc[0][nt][3] - MB)
                     + __expf(acc[1][nt][1] - MB) + __expf(acc[1][nt][3] - MB);
#pragma unroll
            for (int d = 4; d <= 16; d <<= 1) {
                sA += __shfl_xor_sync(0xffffffffu, sA, d);
                sB += __shfl_xor_sync(0xffffffffu, sB, d);
            }
            if (gid == 0) {
                smD[wm * 128 + colL] = sA;
                smD[wm * 128 + colL + 1] = sB;
            }
        }
        __syncthreads();
        if (tid < 128) {
            const float Dv = smD[tid] + smD[128 + tid] + smD[256 + tid] + smD[384 + tid];
            const long o = ((long)z * 16 + blockIdx.y) * S_ + n0 + tid;
            pm[o] = smMF[tid];
            pd[o] = Dv;
        }
    }
}

// ---- fp32 -> split bf16 preconversion ----
__global__ __launch_bounds__(256)
void cvt_split(const float* __restrict__ x, u16* __restrict__ h,
               u16* __restrict__ l, int n4) {
    const int i = blockIdx.x * 256 + threadIdx.x;
    if (i < n4) {
        uint2 hh, ll;
        split4(((const float4*)x)[i], hh, ll);
        ((uint2*)h)[i] = hh;
        ((uint2*)l)[i] = ll;
    }
}

// ---- V transpose per head (split bf16 in, split bf16 out) ----
__global__ __launch_bounds__(256)
void vtrans_kernel(const u16* __restrict__ vh, const u16* __restrict__ vl,
                   u16* __restrict__ th, u16* __restrict__ tl) {
    __shared__ uint32_t t[64][65];
    const int z = blockIdx.y, jt = blockIdx.x * 64;
    const int b = z >> 4, h = z & 15;
    const long src = ((long)b * S_ + jt) * D_ + h * HD_;
    for (int i = threadIdx.x; i < 64 * 64; i += 256) {
        const long idx = src + (long)(i >> 6) * D_ + (i & 63);
        t[i >> 6][i & 63] = (uint32_t)vh[idx] | ((uint32_t)vl[idx] << 16);
    }
    __syncthreads();
    const long dst = (long)z * HD_ * S_ + jt;
    for (int i = threadIdx.x; i < 64 * 64; i += 256) {
        const uint32_t u = t[i & 63][i >> 6];
        const long o = dst + (long)(i >> 6) * S_ + (i & 63);
        th[o] = (u16)(u & 0xFFFF);
        tl[o] = (u16)(u >> 16);
    }
}

// ---- combine column-stats partials across the 16 i-tiles ----
__global__ __launch_bounds__(256)
void redstats_kernel(const float* __restrict__ pm, const float* __restrict__ pd,
                     float* __restrict__ cm, float* __restrict__ cd) {
    const int z = blockIdx.y;
    const int j = blockIdx.x * 256 + threadIdx.x;
    float m = -3.0e38f;
#pragma unroll
    for (int it = 0; it < 16; it++)
        m = fmaxf(m, pm[((long)z * 16 + it) * S_ + j]);
    float d = 0.f;
#pragma unroll
    for (int it = 0; it < 16; it++) {
        const long o = ((long)z * 16 + it) * S_ + j;
        d += pd[o] * __expf(pm[o] - m);
    }
    cm[z * S_ + j] = m;
    cd[z * S_ + j] = d;
}

// ---------------------------------------------------------------------------
extern "C" void kernel_launch(void* const* d_in, const int* in_sizes, int n_in,
                              void* d_out, int out_size)
{
    const float* query = (const float*)d_in[0];
    const float* key_  = (const float*)d_in[1];
    const float* value = (const float*)d_in[2];
    const int*   mask  = (const int*)d_in[3];
    const float* Wq = (const float*)d_in[4];
    const float* bq = (const float*)d_in[5];
    const float* Wk = (const float*)d_in[6];
    const float* bk = (const float*)d_in[7];
    const float* Wv = (const float*)d_in[8];
    const float* bv = (const float*)d_in[9];
    const float* Wp = (const float*)d_in[10];
    const float* bp = (const float*)d_in[11];
    float* out = (float*)d_out;

    u16 *p_cqh, *p_cql, *p_ckh, *p_ckl, *p_cvh, *p_cvl;
    u16 *p_wqh, *p_wql, *p_wkh, *p_wkl, *p_wvh, *p_wvl, *p_wph, *p_wpl;
    u16 *p_qh, *p_ql, *p_kh, *p_kl, *p_vh, *p_vl, *p_vth, *p_vtl, *p_ath, *p_atl;
    float *sc, *ppm, *ppd, *pcm, *pcd;
    cudaGetSymbolAddress((void**)&p_cqh, cqh); cudaGetSymbolAddress((void**)&p_cql, cql);
    cudaGetSymbolAddress((void**)&p_ckh, ckh); cudaGetSymbolAddress((void**)&p_ckl, ckl);
    cudaGetSymbolAddress((void**)&p_cvh, cvh); cudaGetSymbolAddress((void**)&p_cvl, cvl);
    cudaGetSymbolAddress((void**)&p_wqh, wqh); cudaGetSymbolAddress((void**)&p_wql, wql);
    cudaGetSymbolAddress((void**)&p_wkh, wkh); cudaGetSymbolAddress((void**)&p_wkl, wkl);
    cudaGetSymbolAddress((void**)&p_wvh, wvh); cudaGetSymbolAddress((void**)&p_wvl, wvl);
    cudaGetSymbolAddress((void**)&p_wph, wph); cudaGetSymbolAddress((void**)&p_wpl, wpl);
    cudaGetSymbolAddress((void**)&p_qh, qhA);  cudaGetSymbolAddress((void**)&p_ql, qlA);
    cudaGetSymbolAddress((void**)&p_kh, khA);  cudaGetSymbolAddress((void**)&p_kl, klA);
    cudaGetSymbolAddress((void**)&p_vh, vhA);  cudaGetSymbolAddress((void**)&p_vl, vlA);
    cudaGetSymbolAddress((void**)&p_vth, vth); cudaGetSymbolAddress((void**)&p_vtl, vtl);
    cudaGetSymbolAddress((void**)&p_ath, athA); cudaGetSymbolAddress((void**)&p_atl, atlA);
    cudaGetSymbolAddress((void**)&sc, g_sc);
    cudaGetSymbolAddress((void**)&ppm, g_pm);  cudaGetSymbolAddress((void**)&ppd, g_pd);
    cudaGetSymbolAddress((void**)&pcm, g_cm);  cudaGetSymbolAddress((void**)&pcd, g_cd);

    const int SM_MAIN = 65536;           // NT=128 EPI 0/2
    const int SM_SCR  = 65536 + 4608;    // NT=128 EPI 1 (+stats)
    const int SM_PV   = 32768 + 16384;   // NT=64 SOFTA
    cudaFuncSetAttribute(mma_gemm<128, 2, false>, cudaFuncAttributeMaxDynamicSharedMemorySize, SM_MAIN);
    cudaFuncSetAttribute(mma_gemm<128, 0, false>, cudaFuncAttributeMaxDynamicSharedMemorySize, SM_MAIN);
    cudaFuncSetAttribute(mma_gemm<128, 1, false>, cudaFuncAttributeMaxDynamicSharedMemorySize, SM_SCR);
    cudaFuncSetAttribute(mma_gemm<64, 2, true>,   cudaFuncAttributeMaxDynamicSharedMemorySize, SM_PV);

    const long SD  = (long)S_ * D_;
    const long HSS = 16 * SSl;

    // 1) preconvert inputs + weights to split-bf16
    cvt_split<<<M1_ * D_ / 1024, 256>>>(query, p_cqh, p_cql, M1_ * D_ / 4);
    cvt_split<<<M1_ * D_ / 1024, 256>>>(key_,  p_ckh, p_ckl, M1_ * D_ / 4);
    cvt_split<<<M1_ * D_ / 1024, 256>>>(value, p_cvh, p_cvl, M1_ * D_ / 4);
    cvt_split<<<D_ * D_ / 1024, 256>>>(Wq, p_wqh, p_wql, D_ * D_ / 4);
    cvt_split<<<D_ * D_ / 1024, 256>>>(Wk, p_wkh, p_wkl, D_ * D_ / 4);
    cvt_split<<<D_ * D_ / 1024, 256>>>(Wv, p_wvh, p_wvl, D_ * D_ / 4);
    cvt_split<<<D_ * D_ / 1024, 256>>>(Wp, p_wph, p_wpl, D_ * D_ / 4);

    // 2) projections (split-bf16 out, bias fused)
    dim3 gp(D_ / 128, M1_ / 128, 1);
    mma_gemm<128, 2, false><<<gp, 256, SM_MAIN>>>(p_cqh, p_cql, nullptr, p_wqh, p_wql,
        nullptr, p_qh, p_ql, bq, nullptr, nullptr, nullptr, nullptr, nullptr,
        D_, D_, D_, D_, 0, 0, 0, 0, 0, 0, 0.f);
    mma_gemm<128, 2, false><<<gp, 256, SM_MAIN>>>(p_ckh, p_ckl, nullptr, p_wkh, p_wkl,
        nullptr, p_kh, p_kl, bk, nullptr, nullptr, nullptr, nullptr, nullptr,
        D_, D_, D_, D_, 0, 0, 0, 0, 0, 0, 0.f);
    mma_gemm<128, 2, false><<<gp, 256, SM_MAIN>>>(p_cvh, p_cvl, nullptr, p_wvh, p_wvl,
        nullptr, p_vh, p_vl, bv, nullptr, nullptr, nullptr, nullptr, nullptr,
        D_, D_, D_, D_, 0, 0, 0, 0, 0, 0, 0.f);

    // 3) V transpose per head
    vtrans_kernel<<<dim3(S_ / 64, BHN), 256>>>(p_vh, p_vl, p_vth, p_vtl);

    // 4) scores = 0.25 * q k^T, mask, + column-stats partials
    mma_gemm<128, 1, false><<<dim3(S_ / 128, S_ / 128, BHN), 256, SM_SCR>>>(
        p_qh, p_ql, nullptr, p_kh, p_kl,
        sc, nullptr, nullptr, nullptr, mask, nullptr, nullptr, ppm, ppd,
        D_, D_, S_, HD_, SD, HD_, SD, HD_, HSS, SSl, 0.25f);

    // 5) reduce partials -> cm, cd
    redstats_kernel<<<dim3(S_ / 256, BHN), 256>>>(ppm, ppd, pcm, pcd);

    // 6) attn @ V (softmax fused into A loader), split-bf16 out
    mma_gemm<64, 2, true><<<dim3(1, S_ / 128, BHN), 256, SM_PV>>>(
        nullptr, nullptr, sc, p_vth, p_vtl,
        nullptr, p_ath, p_atl, nullptr, nullptr, pcm, pcd, nullptr, nullptr,
        S_, S_, D_, S_, HSS, SSl, (long)16 * HD_ * S_, (long)HD_ * S_, SD, HD_, 0.f);

    // 7) output projection -> d_out (fp32 + bias)
    mma_gemm<128, 0, false><<<gp, 256, SM_MAIN>>>(p_ath, p_atl, nullptr, p_wph, p_wpl,
        out, nullptr, nullptr, bp, nullptr, nullptr, nullptr, nullptr, nullptr,
        D_, D_, D_, D_, 0, 0, 0, 0, 0, 0, 0.f);
}

// round 8
// speedup vs baseline: 3.6636x; 1.0177x over previous
#include <cuda_runtime.h>
#include <cuda_bf16.h>
#include <cuda_fp16.h>
#include <stdint.h>

#define S_  2048
#define D_  1024
#define HD_ 64
#define M1_ 4096
#define BHN 32
#define SSl ((long)S_ * S_)

typedef unsigned short u16;

// ---------------- static scratch ----------------
__device__ u16 cqh[M1_ * D_], cql[M1_ * D_];   // converted query
__device__ u16 ckh[M1_ * D_], ckl[M1_ * D_];   // converted key
__device__ u16 cvh[M1_ * D_], cvl[M1_ * D_];   // converted value
__device__ u16 wqh[D_ * D_], wql[D_ * D_];
__device__ u16 wkh[D_ * D_], wkl[D_ * D_];
__device__ u16 wvh[D_ * D_], wvl[D_ * D_];
__device__ u16 wph[D_ * D_], wpl[D_ * D_];
__device__ u16 qhA[M1_ * D_], qlA[M1_ * D_];   // projected Q (split)
__device__ u16 khA[M1_ * D_], klA[M1_ * D_];   // projected K
__device__ u16 vhA[M1_ * D_], vlA[M1_ * D_];   // projected V
__device__ u16 vth[BHN * HD_ * S_], vtl[BHN * HD_ * S_];  // V^T per head
__device__ u16 athA[M1_ * D_], atlA[M1_ * D_]; // attn output (split)
__device__ u16 g_e[(long)BHN * SSl];           // e' = exp(s - m_tile), fp16 (256 MB)
__device__ float g_pm[BHN * 16 * S_], g_pd[BHN * 16 * S_];
__device__ float g_cm[BHN * S_], g_cd[BHN * S_];

// ---------------- helpers ----------------
__device__ __forceinline__ uint32_t smem_u32(const void* p) {
    uint32_t a;
    asm("{ .reg .u64 t; cvta.to.shared.u64 t, %1; cvt.u32.u64 %0, t; }" : "=r"(a) : "l"(p));
    return a;
}
__device__ __forceinline__ void cpa16(uint32_t d, const void* s) {
    asm volatile("cp.async.cg.shared.global [%0], [%1], 16;" :: "r"(d), "l"(s));
}
#define CPC()  asm volatile("cp.async.commit_group;" ::: "memory")
#define CPW1() asm volatile("cp.async.wait_group 1;" ::: "memory")
#define CPW0() asm volatile("cp.async.wait_group 0;" ::: "memory")

__device__ __forceinline__ void ldm_x4(uint32_t* r, uint32_t addr) {
    asm volatile("ldmatrix.sync.aligned.m8n8.x4.shared.b16 {%0,%1,%2,%3}, [%4];"
                 : "=r"(r[0]), "=r"(r[1]), "=r"(r[2]), "=r"(r[3]) : "r"(addr));
}
__device__ __forceinline__ void ldm_x2(uint32_t* r, uint32_t addr) {
    asm volatile("ldmatrix.sync.aligned.m8n8.x2.shared.b16 {%0,%1}, [%2];"
                 : "=r"(r[0]), "=r"(r[1]) : "r"(addr));
}
__device__ __forceinline__ void mma16816(float* c, const uint32_t* a, const uint32_t* b) {
    asm volatile(
        "mma.sync.aligned.m16n8k16.row.col.f32.bf16.bf16.f32 "
        "{%0,%1,%2,%3}, {%4,%5,%6,%7}, {%8,%9}, {%0,%1,%2,%3};"
        : "+f"(c[0]), "+f"(c[1]), "+f"(c[2]), "+f"(c[3])
        : "r"(a[0]), "r"(a[1]), "r"(a[2]), "r"(a[3]), "r"(b[0]), "r"(b[1]));
}
__device__ __forceinline__ uint32_t pk2(float a, float b) {
    __nv_bfloat162 t = __floats2bfloat162_rn(a, b);
    return *(uint32_t*)&t;
}
__device__ __forceinline__ void split2(float a, float b, uint32_t& h, uint32_t& l) {
    __nv_bfloat16 h0 = __float2bfloat16(a), h1 = __float2bfloat16(b);
    h = ((uint32_t)__bfloat16_as_ushort(h1) << 16) | __bfloat16_as_ushort(h0);
    l = pk2(a - __bfloat162float(h0), b - __bfloat162float(h1));
}
__device__ __forceinline__ void split4(float4 v, uint2& h, uint2& l) {
    split2(v.x, v.y, h.x, l.x);
    split2(v.z, v.w, h.y, l.y);
}

// ---------------------------------------------------------------------------
// Pipelined split-bf16 mma.sync GEMM: C[128, NT] = A[128,K] . B[NT,K]^T
//   C ~= AhBh + AhBl + AlBh (fp32 accum)
// !SOFTA: A preconverted (Ah,Al) bf16 via cp.async.
// SOFTA:  A = fp16 e' (in Ah); p = e' * scale_j, scale_j from smem table
//         (scale_j = exp(pm_tile[j] - m[j]) / d[j], computed 32 lanes/chunk).
// EPI 0: fp32 out + bias; 1: scores -> fp16 e' out + column stats partials;
//     2: split-bf16 out (+bias)
// ---------------------------------------------------------------------------
template<int NT, int EPI, bool SOFTA>
__global__ __launch_bounds__(256, 2)
void mma_gemm(const u16* __restrict__ Ah, const u16* __restrict__ Al,
              const u16* __restrict__ Bh, const u16* __restrict__ Bl,
              float* __restrict__ Cf, u16* __restrict__ Ch, u16* __restrict__ Cl,
              const float* __restrict__ bias, const int* __restrict__ mask,
              const float* __restrict__ cm, const float* __restrict__ cd,
              float* __restrict__ pm, float* __restrict__ pd,
              int lda, int ldb, int ldc, int K,
              long sAb, long sAh_, long sBb, long sBh_, long sCb, long sCh_,
              float scale)
{
    constexpr int WN  = NT / 2;
    constexpr int NB  = WN / 8;
    constexpr int BSZ = NT * 64;      // bytes per B array per stage
    constexpr int BOFF = 32768;       // A stages: 2 x (8K hi + 8K lo)
    extern __shared__ __align__(128) uint8_t sm[];
    __shared__ float scaleS[2][32];
    const uint32_t smb = smem_u32(sm);

    const int tid = threadIdx.x, wid = tid >> 5, lane = tid & 31;
    const int wm = wid >> 1, wn = wid & 1;
    const int z = blockIdx.z, bb = z >> 4, hh = z & 15;
    const int m0 = blockIdx.y * 128, n0 = blockIdx.x * NT;

    Ah += bb * sAb + hh * sAh_;
    if (!SOFTA) Al += bb * sAb + hh * sAh_;
    if (SOFTA) {
        cm += (long)z * S_;  cd += (long)z * S_;
        pm += ((long)z * 16 + blockIdx.y) * S_;
    }
    Bh += bb * sBb + hh * sBh_;  Bl += bb * sBb + hh * sBh_;
    if (EPI == 0)      { Cf += bb * sCb + hh * sCh_; }
    else if (EPI == 1) { Ch += bb * sCb + hh * sCh_; }
    else               { Ch += bb * sCb + hh * sCh_; Cl += bb * sCb + hh * sCh_; }

    uint4 areg4[2];
    auto issueA = [&](int c, int s) {
#pragma unroll
        for (int p = 0; p < 2; p++) {
            const int e = p * 256 + tid, r = e >> 2, ch = e & 3;
            const uint32_t off = (uint32_t)(r * 4 + (ch ^ ((r >> 1) & 3))) * 16;
            const long src = (long)(m0 + r) * lda + c * 32 + ch * 8;
            cpa16(smb + s * 16384 + off, Ah + src);
            cpa16(smb + s * 16384 + 8192 + off, Al + src);
        }
    };
    auto issueB = [&](int c, int s) {
#pragma unroll
        for (int p = 0; p < NT * 4 / 256; p++) {
            const int e = p * 256 + tid, r = e >> 2, ch = e & 3;
            const uint32_t off = (uint32_t)(r * 4 + (ch ^ ((r >> 1) & 3))) * 16;
            const long src = (long)(n0 + r) * ldb + c * 32 + ch * 8;
            cpa16(smb + BOFF + s * 2 * BSZ + off, Bh + src);
            cpa16(smb + BOFF + s * 2 * BSZ + BSZ + off, Bl + src);
        }
    };
    auto prefA = [&](int c) {   // SOFTA: load fp16 e' tile (128 x 32)
#pragma unroll
        for (int p = 0; p < 2; p++) {
            const int e = p * 256 + tid, r = e >> 2, j8 = (e & 3) * 8;
            areg4[p] = *(const uint4*)(Ah + (long)(m0 + r) * lda + c * 32 + j8);
        }
    };
    auto stsA = [&](int c, int s) {  // SOFTA: p = e' * scale_j, split, STS
#pragma unroll
        for (int p = 0; p < 2; p++) {
            const int e = p * 256 + tid, r = e >> 2, j8 = (e & 3) * 8;
            const __half2* hp = (const __half2*)&areg4[p];
            uint4 hi, lo;
            uint32_t* hw = (uint32_t*)&hi;
            uint32_t* lw = (uint32_t*)&lo;
#pragma unroll
            for (int t = 0; t < 4; t++) {
                const float2 f = __half22float2(hp[t]);
                const float pa = f.x * scaleS[c & 1][j8 + 2 * t];
                const float pb = f.y * scaleS[c & 1][j8 + 2 * t + 1];
                split2(pa, pb, hw[t], lw[t]);
            }
            const int ch = j8 >> 3;
            const uint32_t off = (uint32_t)(r * 4 + (ch ^ ((r >> 1) & 3))) * 16;
            *(uint4*)(sm + s * 16384 + off) = hi;
            *(uint4*)(sm + s * 16384 + 8192 + off) = lo;
        }
    };

    // ldmatrix lane addressing
    const int rA = wm * 32 + (lane & 15);
    const int cpA = (lane >> 4) & 1;
    const int swA = (rA >> 1) & 3;
    const int rB = wn * WN + (lane & 7);
    const int cpB = (lane >> 3) & 1;
    const int swB = (rB >> 1) & 3;

    float acc[2][NB][4];
#pragma unroll
    for (int i = 0; i < 2; i++)
#pragma unroll
        for (int j = 0; j < NB; j++)
#pragma unroll
            for (int e = 0; e < 4; e++) acc[i][j][e] = 0.f;

    const int nch = K / 32;
    if (SOFTA) {
        prefA(0);
        if (tid < 32) {
            const int j = tid;
            scaleS[0][tid] = __expf(pm[j] - cm[j]) / cd[j];
        }
    } else {
        issueA(0, 0);
    }
    issueB(0, 0);
    CPC();
    if (SOFTA) __syncthreads();   // scaleS[0] visible before stsA(0)

    for (int c = 0; c < nch; c++) {
        const int s = c & 1;
        if (SOFTA) stsA(c, s);
        const bool more = (c + 1 < nch);
        if (more) {
            if (!SOFTA) issueA(c + 1, s ^ 1);
            issueB(c + 1, s ^ 1);
            CPC();
            if (SOFTA) prefA(c + 1);
            CPW1();
        } else {
            CPW0();
        }
        __syncthreads();

        if (SOFTA && more && tid < 32) {   // scale table for chunk c+1
            const int j = (c + 1) * 32 + tid;
            scaleS[s ^ 1][tid] = __expf(pm[j] - cm[j]) / cd[j];
        }

        const uint32_t aBase = smb + s * 16384;
        const uint32_t bBase = smb + BOFF + s * 2 * BSZ;
#pragma unroll
        for (int ks = 0; ks < 2; ks++) {
            const int cA = (2 * ks + cpA) ^ swA;
            uint32_t ah0[4], ah1[4], al0[4], al1[4];
            ldm_x4(ah0, aBase + (rA * 4 + cA) * 16);
            ldm_x4(ah1, aBase + ((rA + 16) * 4 + cA) * 16);
            ldm_x4(al0, aBase + 8192 + (rA * 4 + cA) * 16);
            ldm_x4(al1, aBase + 8192 + ((rA + 16) * 4 + cA) * 16);
            const int cB = (2 * ks + cpB) ^ swB;
#pragma unroll
            for (int nt = 0; nt < NB; nt++) {
                uint32_t bh[2], bl[2];
                const uint32_t ob = ((rB + nt * 8) * 4 + cB) * 16;
                ldm_x2(bh, bBase + ob);
                ldm_x2(bl, bBase + BSZ + ob);
                mma16816(acc[0][nt], ah0, bh);
                mma16816(acc[0][nt], ah0, bl);
                mma16816(acc[0][nt], al0, bh);
                mma16816(acc[1][nt], ah1, bh);
                mma16816(acc[1][nt], ah1, bl);
                mma16816(acc[1][nt], al1, bh);
            }
        }
        __syncthreads();
    }

    // ---- epilogue ----
    const int gid = lane >> 2, qid = lane & 3;
    if (EPI == 1) {
        float* smM  = (float*)(sm + BOFF + 4 * BSZ);  // [4][128]
        float* smMF = smM + 512;                      // [128]
        float* smD  = smMF + 128;                     // [4][128]

        // 1: scale + mask into acc
#pragma unroll
        for (int mt = 0; mt < 2; mt++) {
            const int r0 = m0 + wm * 32 + mt * 16 + gid;
#pragma unroll
            for (int nt = 0; nt < NB; nt++) {
                const int col = n0 + wn * WN + nt * 8 + qid * 2;
                const int2 ma = *(const int2*)(mask + (long)r0 * S_ + col);
                const int2 mb = *(const int2*)(mask + (long)(r0 + 8) * S_ + col);
                acc[mt][nt][0] = ma.x ? acc[mt][nt][0] * scale : -10000.0f;
                acc[mt][nt][1] = ma.y ? acc[mt][nt][1] * scale : -10000.0f;
                acc[mt][nt][2] = mb.x ? acc[mt][nt][2] * scale : -10000.0f;
                acc[mt][nt][3] = mb.y ? acc[mt][nt][3] * scale : -10000.0f;
            }
        }
        // 2: per-tile column max over the 128 rows
#pragma unroll
        for (int nt = 0; nt < NB; nt++) {
            float mA = fmaxf(fmaxf(acc[0][nt][0], acc[0][nt][2]),
                             fmaxf(acc[1][nt][0], acc[1][nt][2]));
            float mB = fmaxf(fmaxf(acc[0][nt][1], acc[0][nt][3]),
                             fmaxf(acc[1][nt][1], acc[1][nt][3]));
#pragma unroll
            for (int d = 4; d <= 16; d <<= 1) {
                mA = fmaxf(mA, __shfl_xor_sync(0xffffffffu, mA, d));
                mB = fmaxf(mB, __shfl_xor_sync(0xffffffffu, mB, d));
            }
            if (gid == 0) {
                const int colL = wn * WN + nt * 8 + qid * 2;
                smM[wm * 128 + colL] = mA;
                smM[wm * 128 + colL + 1] = mB;
            }
        }
        __syncthreads();
        if (tid < 128) {
            smMF[tid] = fmaxf(fmaxf(smM[tid], smM[128 + tid]),
                              fmaxf(smM[256 + tid], smM[384 + tid]));
        }
        __syncthreads();
        // 3: e' = exp(s - m_tile): store fp16 + accumulate column sums
#pragma unroll
        for (int nt = 0; nt < NB; nt++) {
            const int colL = wn * WN + nt * 8 + qid * 2;
            const float MA = smMF[colL], MB = smMF[colL + 1];
            float sA = 0.f, sB = 0.f;
#pragma unroll
            for (int mt = 0; mt < 2; mt++) {
                const int r0 = m0 + wm * 32 + mt * 16 + gid;
                const float e0 = __expf(acc[mt][nt][0] - MA);
                const float e1 = __expf(acc[mt][nt][1] - MB);
                const float e2 = __expf(acc[mt][nt][2] - MA);
                const float e3 = __expf(acc[mt][nt][3] - MB);
                sA += e0 + e2;  sB += e1 + e3;
                const __half2 p01 = __floats2half2_rn(e0, e1);
                const __half2 p23 = __floats2half2_rn(e2, e3);
                *(uint32_t*)(Ch + (long)r0 * ldc + n0 + colL) = *(const uint32_t*)&p01;
                *(uint32_t*)(Ch + (long)(r0 + 8) * ldc + n0 + colL) = *(const uint32_t*)&p23;
            }
#pragma unroll
            for (int d = 4; d <= 16; d <<= 1) {
                sA += __shfl_xor_sync(0xffffffffu, sA, d);
                sB += __shfl_xor_sync(0xffffffffu, sB, d);
            }
            if (gid == 0) {
                smD[wm * 128 + colL] = sA;
                smD[wm * 128 + colL + 1] = sB;
            }
        }
        __syncthreads();
        if (tid < 128) {
            const float Dv = smD[tid] + smD[128 + tid] + smD[256 + tid] + smD[384 + tid];
            const long o = ((long)z * 16 + blockIdx.y) * S_ + n0 + tid;
            pm[o] = smMF[tid];
            pd[o] = Dv;
        }
    } else {
#pragma unroll
        for (int mt = 0; mt < 2; mt++) {
            const int r0 = m0 + wm * 32 + mt * 16 + gid;
#pragma unroll
            for (int nt = 0; nt < NB; nt++) {
                const int col = n0 + wn * WN + nt * 8 + qid * 2;
                float2 v0 = make_float2(acc[mt][nt][0], acc[mt][nt][1]);
                float2 v1 = make_float2(acc[mt][nt][2], acc[mt][nt][3]);
                if (bias) {
                    const float b0 = bias[col], b1 = bias[col + 1];
                    v0.x += b0; v0.y += b1; v1.x += b0; v1.y += b1;
                }
                if (EPI == 0) {
                    *(float2*)(Cf + (long)r0 * ldc + col) = v0;
                    *(float2*)(Cf + (long)(r0 + 8) * ldc + col) = v1;
                } else {
                    uint32_t h0, l0, h1, l1;
                    split2(v0.x, v0.y, h0, l0);
                    split2(v1.x, v1.y, h1, l1);
                    *(uint32_t*)(Ch + (long)r0 * ldc + col) = h0;
                    *(uint32_t*)(Cl + (long)r0 * ldc + col) = l0;
                    *(uint32_t*)(Ch + (long)(r0 + 8) * ldc + col) = h1;
                    *(uint32_t*)(Cl + (long)(r0 + 8) * ldc + col) = l1;
                }
            }
        }
    }
}

// ---- fp32 -> split bf16 preconversion ----
__global__ __launch_bounds__(256)
void cvt_split(const float* __restrict__ x, u16* __restrict__ h,
               u16* __restrict__ l, int n4) {
    const int i = blockIdx.x * 256 + threadIdx.x;
    if (i < n4) {
        uint2 hh, ll;
        split4(((const float4*)x)[i], hh, ll);
        ((uint2*)h)[i] = hh;
        ((uint2*)l)[i] = ll;
    }
}

// ---- V transpose per head (split bf16 in, split bf16 out) ----
__global__ __launch_bounds__(256)
void vtrans_kernel(const u16* __restrict__ vh, const u16* __restrict__ vl,
                   u16* __restrict__ th, u16* __restrict__ tl) {
    __shared__ uint32_t t[64][65];
    const int z = blockIdx.y, jt = blockIdx.x * 64;
    const int b = z >> 4, h = z & 15;
    const long src = ((long)b * S_ + jt) * D_ + h * HD_;
    for (int i = threadIdx.x; i < 64 * 64; i += 256) {
        const long idx = src + (long)(i >> 6) * D_ + (i & 63);
        t[i >> 6][i & 63] = (uint32_t)vh[idx] | ((uint32_t)vl[idx] << 16);
    }
    __syncthreads();
    const long dst = (long)z * HD_ * S_ + jt;
    for (int i = threadIdx.x; i < 64 * 64; i += 256) {
        const uint32_t u = t[i & 63][i >> 6];
        const long o = dst + (long)(i >> 6) * S_ + (i & 63);
        th[o] = (u16)(u & 0xFFFF);
        tl[o] = (u16)(u >> 16);
    }
}

// ---- combine column-stats partials across the 16 i-tiles ----
__global__ __launch_bounds__(256)
void redstats_kernel(const float* __restrict__ pm, const float* __restrict__ pd,
                     float* __restrict__ cm, float* __restrict__ cd) {
    const int z = blockIdx.y;
    const int j = blockIdx.x * 256 + threadIdx.x;
    float m = -3.0e38f;
#pragma unroll
    for (int it = 0; it < 16; it++)
        m = fmaxf(m, pm[((long)z * 16 + it) * S_ + j]);
    float d = 0.f;
#pragma unroll
    for (int it = 0; it < 16; it++) {
        const long o = ((long)z * 16 + it) * S_ + j;
        d += pd[o] * __expf(pm[o] - m);
    }
    cm[z * S_ + j] = m;
    cd[z * S_ + j] = d;
}

// ---------------------------------------------------------------------------
extern "C" void kernel_launch(void* const* d_in, const int* in_sizes, int n_in,
                              void* d_out, int out_size)
{
    const float* query = (const float*)d_in[0];
    const float* key_  = (const float*)d_in[1];
    const float* value = (const float*)d_in[2];
    const int*   mask  = (const int*)d_in[3];
    const float* Wq = (const float*)d_in[4];
    const float* bq = (const float*)d_in[5];
    const float* Wk = (const float*)d_in[6];
    const float* bk = (const float*)d_in[7];
    const float* Wv = (const float*)d_in[8];
    const float* bv = (const float*)d_in[9];
    const float* Wp = (const float*)d_in[10];
    const float* bp = (const float*)d_in[11];
    float* out = (float*)d_out;

    u16 *p_cqh, *p_cql, *p_ckh, *p_ckl, *p_cvh, *p_cvl;
    u16 *p_wqh, *p_wql, *p_wkh, *p_wkl, *p_wvh, *p_wvl, *p_wph, *p_wpl;
    u16 *p_qh, *p_ql, *p_kh, *p_kl, *p_vh, *p_vl, *p_vth, *p_vtl, *p_ath, *p_atl;
    u16 *p_e;
    float *ppm, *ppd, *pcm, *pcd;
    cudaGetSymbolAddress((void**)&p_cqh, cqh); cudaGetSymbolAddress((void**)&p_cql, cql);
    cudaGetSymbolAddress((void**)&p_ckh, ckh); cudaGetSymbolAddress((void**)&p_ckl, ckl);
    cudaGetSymbolAddress((void**)&p_cvh, cvh); cudaGetSymbolAddress((void**)&p_cvl, cvl);
    cudaGetSymbolAddress((void**)&p_wqh, wqh); cudaGetSymbolAddress((void**)&p_wql, wql);
    cudaGetSymbolAddress((void**)&p_wkh, wkh); cudaGetSymbolAddress((void**)&p_wkl, wkl);
    cudaGetSymbolAddress((void**)&p_wvh, wvh); cudaGetSymbolAddress((void**)&p_wvl, wvl);
    cudaGetSymbolAddress((void**)&p_wph, wph); cudaGetSymbolAddress((void**)&p_wpl, wpl);
    cudaGetSymbolAddress((void**)&p_qh, qhA);  cudaGetSymbolAddress((void**)&p_ql, qlA);
    cudaGetSymbolAddress((void**)&p_kh, khA);  cudaGetSymbolAddress((void**)&p_kl, klA);
    cudaGetSymbolAddress((void**)&p_vh, vhA);  cudaGetSymbolAddress((void**)&p_vl, vlA);
    cudaGetSymbolAddress((void**)&p_vth, vth); cudaGetSymbolAddress((void**)&p_vtl, vtl);
    cudaGetSymbolAddress((void**)&p_ath, athA); cudaGetSymbolAddress((void**)&p_atl, atlA);
    cudaGetSymbolAddress((void**)&p_e, g_e);
    cudaGetSymbolAddress((void**)&ppm, g_pm);  cudaGetSymbolAddress((void**)&ppd, g_pd);
    cudaGetSymbolAddress((void**)&pcm, g_cm);  cudaGetSymbolAddress((void**)&pcd, g_cd);

    const int SM_MAIN = 65536;           // NT=128 EPI 0/2
    const int SM_SCR  = 65536 + 4608;    // NT=128 EPI 1 (+stats)
    const int SM_PV   = 32768 + 16384;   // NT=64 SOFTA
    cudaFuncSetAttribute(mma_gemm<128, 2, false>, cudaFuncAttributeMaxDynamicSharedMemorySize, SM_MAIN);
    cudaFuncSetAttribute(mma_gemm<128, 0, false>, cudaFuncAttributeMaxDynamicSharedMemorySize, SM_MAIN);
    cudaFuncSetAttribute(mma_gemm<128, 1, false>, cudaFuncAttributeMaxDynamicSharedMemorySize, SM_SCR);
    cudaFuncSetAttribute(mma_gemm<64, 2, true>,   cudaFuncAttributeMaxDynamicSharedMemorySize, SM_PV);

    const long SD  = (long)S_ * D_;
    const long HSS = 16 * SSl;

    // 1) preconvert inputs + weights to split-bf16
    cvt_split<<<M1_ * D_ / 1024, 256>>>(query, p_cqh, p_cql, M1_ * D_ / 4);
    cvt_split<<<M1_ * D_ / 1024, 256>>>(key_,  p_ckh, p_ckl, M1_ * D_ / 4);
    cvt_split<<<M1_ * D_ / 1024, 256>>>(value, p_cvh, p_cvl, M1_ * D_ / 4);
    cvt_split<<<D_ * D_ / 1024, 256>>>(Wq, p_wqh, p_wql, D_ * D_ / 4);
    cvt_split<<<D_ * D_ / 1024, 256>>>(Wk, p_wkh, p_wkl, D_ * D_ / 4);
    cvt_split<<<D_ * D_ / 1024, 256>>>(Wv, p_wvh, p_wvl, D_ * D_ / 4);
    cvt_split<<<D_ * D_ / 1024, 256>>>(Wp, p_wph, p_wpl, D_ * D_ / 4);

    // 2) projections (split-bf16 out, bias fused)
    dim3 gp(D_ / 128, M1_ / 128, 1);
    mma_gemm<128, 2, false><<<gp, 256, SM_MAIN>>>(p_cqh, p_cql, p_wqh, p_wql,
        nullptr, p_qh, p_ql, bq, nullptr, nullptr, nullptr, nullptr, nullptr,
        D_, D_, D_, D_, 0, 0, 0, 0, 0, 0, 0.f);
    mma_gemm<128, 2, false><<<gp, 256, SM_MAIN>>>(p_ckh, p_ckl, p_wkh, p_wkl,
        nullptr, p_kh, p_kl, bk, nullptr, nullptr, nullptr, nullptr, nullptr,
        D_, D_, D_, D_, 0, 0, 0, 0, 0, 0, 0.f);
    mma_gemm<128, 2, false><<<gp, 256, SM_MAIN>>>(p_cvh, p_cvl, p_wvh, p_wvl,
        nullptr, p_vh, p_vl, bv, nullptr, nullptr, nullptr, nullptr, nullptr,
        D_, D_, D_, D_, 0, 0, 0, 0, 0, 0, 0.f);

    // 3) V transpose per head
    vtrans_kernel<<<dim3(S_ / 64, BHN), 256>>>(p_vh, p_vl, p_vth, p_vtl);

    // 4) scores = 0.25 * q k^T, mask -> e' fp16 + column-stats partials
    mma_gemm<128, 1, false><<<dim3(S_ / 128, S_ / 128, BHN), 256, SM_SCR>>>(
        p_qh, p_ql, p_kh, p_kl,
        nullptr, p_e, nullptr, nullptr, mask, nullptr, nullptr, ppm, ppd,
        D_, D_, S_, HD_, SD, HD_, SD, HD_, HSS, SSl, 0.25f);

    // 5) reduce partials -> cm, cd
    redstats_kernel<<<dim3(S_ / 256, BHN), 256>>>(ppm, ppd, pcm, pcd);

    // 6) attn @ V (p = e' * scale_j from smem table), split-bf16 out
    mma_gemm<64, 2, true><<<dim3(1, S_ / 128, BHN), 256, SM_PV>>>(
        p_e, nullptr, p_vth, p_vtl,
        nullptr, p_ath, p_atl, nullptr, nullptr, pcm, pcd, ppm, nullptr,
        S_, S_, D_, S_, HSS, SSl, (long)16 * HD_ * S_, (long)HD_ * S_, SD, HD_, 0.f);

    // 7) output projection -> d_out (fp32 + bias)
    mma_gemm<128, 0, false><<<gp, 256, SM_MAIN>>>(p_ath, p_atl, p_wph, p_wpl,
        out, nullptr, nullptr, bp, nullptr, nullptr, nullptr, nullptr, nullptr,
        D_, D_, D_, D_, 0, 0, 0, 0, 0, 0, 0.f);
}